// round 4
// baseline (speedup 1.0000x reference)
#include <cuda_runtime.h>
#include <math.h>

#define BB 128
#define TT 512
#define DD 300
#define HH 300
#define NG 1200   // 4*H

// ---- device scratch (static: the sanctioned alloc-free path) ----
__device__ float g_h[2][BB*HH];                 // double-buffered hidden state
__device__ float g_c[BB*HH];                    // cell state (owner-exclusive, single buffer)
__device__ float g_xz[(size_t)BB*TT*NG];        // precomputed x@Wx + b_lstm, [b][t][1200]

#define STEP_SMEM_FLOATS (9600 + 9600 + 1024 + 64)
#define STEP_SMEM_BYTES  (STEP_SMEM_FLOATS * 4)

// ---------------------------------------------------------------------------
// init: zero h (both buffers) and c
// ---------------------------------------------------------------------------
__global__ void init_kernel() {
    int i = blockIdx.x * blockDim.x + threadIdx.x;
    if (i < BB*HH) {
        g_h[0][i] = 0.f;
        g_h[1][i] = 0.f;
        g_c[i]    = 0.f;
    }
}

// ---------------------------------------------------------------------------
// precompute: g_xz[b][t][n] = embedding[ids[b][t]] @ W_lstm[0:300, n] + b_lstm[n]
// grid (19 n-tiles of 64, 4 t-tiles of 128, 128 b), 256 threads
// Early-exit whole CTA when this batch is already finished at t0.
// ---------------------------------------------------------------------------
__global__ __launch_bounds__(256) void precompute_kernel(
    const int*   __restrict__ ids,
    const int*   __restrict__ lengths,
    const float* __restrict__ emb,
    const float* __restrict__ W,
    const float* __restrict__ bl)
{
    const int b  = blockIdx.z;
    const int t0 = blockIdx.y * 128;
    const int n0 = blockIdx.x * 64;
    if (lengths[b] <= t0) return;   // uniform across CTA, before any syncthreads

    __shared__ float As[16][128];   // k-major A tile (embedding rows)
    __shared__ float Bs[16][64];    // k x n tile of W_lstm (x-part rows)
    __shared__ int   toks[128];

    const int tid = threadIdx.x;
    if (tid < 128) toks[tid] = ids[b*TT + t0 + tid];

    const int tx = tid & 15;   // n: 4 cols each  -> 64
    const int ty = tid >> 4;   // m: 8 rows each  -> 128
    float acc[8][4];
    #pragma unroll
    for (int i = 0; i < 8; i++)
        #pragma unroll
        for (int j = 0; j < 4; j++) acc[i][j] = 0.f;

    for (int k0 = 0; k0 < 300; k0 += 16) {
        __syncthreads();
        // A tile: 128 rows x 16 k, gathered from embedding (float4 per load)
        for (int l = tid; l < 512; l += 256) {
            int r  = l >> 2;
            int kq = l & 3;
            int k  = k0 + kq * 4;
            float4 v = make_float4(0.f, 0.f, 0.f, 0.f);
            if (k < 300) v = *(const float4*)(emb + (size_t)toks[r]*DD + k);
            As[kq*4+0][r] = v.x;
            As[kq*4+1][r] = v.y;
            As[kq*4+2][r] = v.z;
            As[kq*4+3][r] = v.w;
        }
        // B tile: 16 k x 64 n
        {
            int l  = tid;            // 256 = 16*16
            int kk = l >> 4;
            int q  = l & 15;
            int k  = k0 + kk;
            int n  = n0 + q * 4;
            float4 v = make_float4(0.f, 0.f, 0.f, 0.f);
            if (k < 300 && n < NG) v = *(const float4*)(W + (size_t)k*NG + n);
            *(float4*)&Bs[kk][q*4] = v;
        }
        __syncthreads();
        #pragma unroll
        for (int kk = 0; kk < 16; kk++) {
            float4 bv = *(const float4*)&Bs[kk][tx*4];
            float4 a0 = *(const float4*)&As[kk][ty*8];
            float4 a1 = *(const float4*)&As[kk][ty*8 + 4];
            float am[8] = {a0.x, a0.y, a0.z, a0.w, a1.x, a1.y, a1.z, a1.w};
            #pragma unroll
            for (int i = 0; i < 8; i++) {
                acc[i][0] += am[i] * bv.x;
                acc[i][1] += am[i] * bv.y;
                acc[i][2] += am[i] * bv.z;
                acc[i][3] += am[i] * bv.w;
            }
        }
    }

    const int n = n0 + tx * 4;
    if (n < NG) {
        float4 blv = *(const float4*)(bl + n);
        #pragma unroll
        for (int i = 0; i < 8; i++) {
            int t = t0 + ty*8 + i;
            float4 o;
            o.x = acc[i][0] + blv.x;
            o.y = acc[i][1] + blv.y;
            o.z = acc[i][2] + blv.z;
            o.w = acc[i][3] + blv.w;
            *(float4*)(g_xz + ((size_t)b*TT + t)*NG + n) = o;
        }
    }
}

// ---------------------------------------------------------------------------
// step: one recurrence timestep.
// grid (38 unit-tiles of 8, 4 batch-tiles of 32), 128 threads, dyn smem.
// CTA computes z_h = h_prev[32 x 300] @ W_h[:, {g*300+u}] for its 8 units x 4
// gates, adds precomputed xz, does gate math, writes c and next-buffer h.
// Masked rows copy h forward so the double buffer stays coherent.
//
// INVARIANT (consumed by final_kernel): when a tile retires at t == maxlen
// (maxlen = max of its 32 lengths), the final state of ALL its rows lives in
// buffer (maxlen & 1): last write was at t = maxlen-1 into buffer
// ((maxlen-1)&1)^1 = maxlen&1, and frozen rows were copy-forwarded on every
// step before that. maxlen == 512 gives buffer 0, consistent with the full
// loop. final_kernel recomputes maxlen per tile and reads the right buffer.
// ---------------------------------------------------------------------------
__global__ __launch_bounds__(128) void step_kernel(
    int t,
    const float* __restrict__ W,
    const int*   __restrict__ lengths)
{
    extern __shared__ float sm[];
    float* hs  = sm;               // [32][300]
    float* wsT = sm + 9600;        // [32 n][300 k]  (n-major for vectorized k reads)
    float* zs  = sm + 19200;       // [32 m][32 n]
    int*   sl  = (int*)(sm + 20224); // [33] lengths + max

    const int u0  = blockIdx.x * 8;
    const int m0  = blockIdx.y * 32;
    const int tid = threadIdx.x;

    if (tid < 32) sl[tid] = lengths[m0 + tid];
    __syncthreads();
    if (tid < 32) {
        int v = sl[tid];
        #pragma unroll
        for (int o = 16; o; o >>= 1) v = max(v, __shfl_xor_sync(0xffffffffu, v, o));
        if (tid == 0) sl[32] = v;
    }
    __syncthreads();
    if (t >= sl[32]) return;   // tile retired; final state is in buffer (sl[32]&1)

    const int    p      = t & 1;
    const float* hread  = g_h[p];
    float*       hwrite = g_h[p ^ 1];

    // hs <- 32 contiguous rows of hread
    {
        const float4* gh4  = (const float4*)(hread + (size_t)m0 * HH);
        float4*       hs4w = (float4*)hs;
        for (int l = tid; l < 2400; l += 128) hs4w[l] = gh4[l];
    }
    // wsT[n][k] <- W_lstm[300+k][g*300 + u0+uu],  n = g*8+uu
    for (int l = tid; l < 9600; l += 128) {
        int k  = l >> 5;
        int nn = l & 31;
        int u  = u0 + (nn & 7);
        int g  = nn >> 3;
        wsT[nn*HH + k] = (u < HH) ? W[(size_t)(HH + k)*NG + g*HH + u] : 0.f;
    }
    __syncthreads();

    const int tx = tid & 15;   // n: 2 each -> 32
    const int ty = tid >> 4;   // m: 4 each -> 32
    const int mr = ty * 4;
    const int nc = tx * 2;
    float acc[4][2];
    #pragma unroll
    for (int i = 0; i < 4; i++) { acc[i][0] = 0.f; acc[i][1] = 0.f; }

    const float4* hs4 = (const float4*)hs;
    const float4* ws4 = (const float4*)wsT;
    #pragma unroll 3
    for (int q = 0; q < 75; q++) {
        float4 w0 = ws4[(nc + 0)*75 + q];
        float4 w1 = ws4[(nc + 1)*75 + q];
        #pragma unroll
        for (int i = 0; i < 4; i++) {
            float4 hv = hs4[(mr + i)*75 + q];
            acc[i][0] += hv.x*w0.x + hv.y*w0.y + hv.z*w0.z + hv.w*w0.w;
            acc[i][1] += hv.x*w1.x + hv.y*w1.y + hv.z*w1.z + hv.w*w1.w;
        }
    }
    #pragma unroll
    for (int i = 0; i < 4; i++) {
        zs[(mr + i)*32 + nc]     = acc[i][0];
        zs[(mr + i)*32 + nc + 1] = acc[i][1];
    }
    __syncthreads();

    // epilogue: 256 (m,u) pairs over 128 threads
    for (int l = tid; l < 256; l += 128) {
        int m  = l >> 3;
        int uu = l & 7;
        int u  = u0 + uu;
        if (u >= HH) continue;
        int b    = m0 + m;
        int hidx = b*HH + u;
        if (t < sl[m]) {
            const float* xzp = g_xz + ((size_t)b*TT + t)*NG + u;
            float zi = zs[m*32 + 0*8 + uu] + xzp[0*HH];
            float zj = zs[m*32 + 1*8 + uu] + xzp[1*HH];
            float zf = zs[m*32 + 2*8 + uu] + xzp[2*HH];
            float zo = zs[m*32 + 3*8 + uu] + xzp[3*HH];
            float si = 1.f / (1.f + expf(-zi));
            float sf = 1.f / (1.f + expf(-(zf + 1.f)));   // FORGET_BIAS = 1
            float so = 1.f / (1.f + expf(-zo));
            float tj = tanhf(zj);
            float cold = g_c[hidx];
            float cnew = cold * sf + si * tj;
            float hnew = tanhf(cnew) * so;
            g_c[hidx]    = cnew;
            hwrite[hidx] = hnew;
        } else {
            hwrite[hidx] = hs[m*HH + u];   // carry frozen state into next buffer
        }
    }
}

// ---------------------------------------------------------------------------
// final: logits = h_final @ W_dense + b_dense ; loss = mean NLL(log_softmax)
// Per the step-kernel invariant, row b's final hidden state lives in buffer
// (maxlen_of_its_32row_tile & 1). Recompute that here from lengths.
// ---------------------------------------------------------------------------
__global__ void final_kernel(
    const float* __restrict__ Wd,
    const float* __restrict__ bd,
    const int*   __restrict__ labels,
    const int*   __restrict__ lengths,
    float*       __restrict__ out,
    int out_size)
{
    __shared__ float red[128];
    __shared__ int   slen[128];
    int b = threadIdx.x;
    slen[b] = lengths[b];
    __syncthreads();

    // max length over this row's 32-row tile -> which buffer holds final h
    int tile0 = b & ~31;
    int maxlen = 0;
    #pragma unroll 8
    for (int i = 0; i < 32; i++) maxlen = max(maxlen, slen[tile0 + i]);
    const float* h = g_h[maxlen & 1] + b*HH;

    float a0 = bd[0], a1 = bd[1], a2 = bd[2];
    for (int k = 0; k < HH; k++) {
        float hv = h[k];
        a0 += hv * Wd[k*3 + 0];
        a1 += hv * Wd[k*3 + 1];
        a2 += hv * Wd[k*3 + 2];
    }
    float mx  = fmaxf(a0, fmaxf(a1, a2));
    float lse = mx + logf(expf(a0 - mx) + expf(a1 - mx) + expf(a2 - mx));
    int   lab = labels[b];
    float sel = (lab == 0) ? a0 : ((lab == 1) ? a1 : a2);
    float nll = lse - sel;

    int off = (out_size >= 385) ? 1 : 0;
    if (out_size >= 384) {
        out[off + b*3 + 0] = a0;
        out[off + b*3 + 1] = a1;
        out[off + b*3 + 2] = a2;
    }
    red[b] = nll;
    __syncthreads();
    for (int s = 64; s; s >>= 1) {
        if (b < s) red[b] += red[b + s];
        __syncthreads();
    }
    if (b == 0 && (off == 1 || out_size < 384)) out[0] = red[0] * (1.f / 128.f);
}

// ---------------------------------------------------------------------------
// launch
// ---------------------------------------------------------------------------
extern "C" void kernel_launch(void* const* d_in, const int* in_sizes, int n_in,
                              void* d_out, int out_size)
{
    const int*   ids     = (const int*)  d_in[0];
    const int*   lengths = (const int*)  d_in[1];
    const int*   labels  = (const int*)  d_in[2];
    const float* emb     = (const float*)d_in[3];
    const float* W       = (const float*)d_in[4];
    const float* bl      = (const float*)d_in[5];
    const float* Wd      = (const float*)d_in[6];
    const float* bd      = (const float*)d_in[7];
    float* out = (float*)d_out;

    cudaFuncSetAttribute(step_kernel,
                         cudaFuncAttributeMaxDynamicSharedMemorySize,
                         STEP_SMEM_BYTES);

    init_kernel<<<(BB*HH + 255)/256, 256>>>();
    precompute_kernel<<<dim3(19, 4, BB), 256>>>(ids, lengths, emb, W, bl);
    for (int t = 0; t < TT; t++)
        step_kernel<<<dim3(38, 4), 128, STEP_SMEM_BYTES>>>(t, W, lengths);
    final_kernel<<<1, 128>>>(Wd, bd, labels, lengths, out, out_size);
}

// round 5
// speedup vs baseline: 1.5283x; 1.5283x over previous
#include <cuda_runtime.h>
#include <math.h>

#define BB 128
#define TT 512
#define DD 300
#define HH 300
#define NG 1200   // 4*H
#define NCTAS 148 // 4 m-tiles x 37 n-tiles -> exactly 1 CTA/SM (residency!)
#define NTIL 37

// ---- device scratch (static: the sanctioned alloc-free path) ----
__device__ float g_h[2][BB*HH];          // double-buffered hidden state
__device__ float g_c[BB*HH];             // cell state
__device__ float g_xz[(size_t)BB*TT*NG]; // precomputed x@Wx + b_lstm
__device__ unsigned int g_bar;           // grid barrier counter (monotonic per launch)

// smem layout (floats)
#define SM_HS   0        // [32][300] h tile
#define SM_WST  9600     // [32 n][300 k] base W slice (n = g*8+uu)
#define SM_WSX  19200    // [4 g][300 k] extra-unit W cols
#define SM_ZS   20400    // [32 m][32 n] base z
#define SM_ZSX  21424    // [32 m][4 g]  extra z
#define SM_SL   21552    // [33] lengths + max
#define SM_TOT  21592
#define PERS_SMEM_BYTES (SM_TOT*4)

// ---------------------------------------------------------------------------
__global__ void init_kernel() {
    int i = blockIdx.x * blockDim.x + threadIdx.x;
    if (i < BB*HH) {
        g_h[0][i] = 0.f;
        g_h[1][i] = 0.f;
        g_c[i]    = 0.f;
    }
    if (blockIdx.x == 0 && threadIdx.x == 0) g_bar = 0u;
}

// ---------------------------------------------------------------------------
// precompute: g_xz[b][t][n] = embedding[ids[b][t]] @ W_lstm[0:300, n] + b_lstm[n]
// (unchanged from passing version)
// ---------------------------------------------------------------------------
__global__ __launch_bounds__(256) void precompute_kernel(
    const int*   __restrict__ ids,
    const int*   __restrict__ lengths,
    const float* __restrict__ emb,
    const float* __restrict__ W,
    const float* __restrict__ bl)
{
    const int b  = blockIdx.z;
    const int t0 = blockIdx.y * 128;
    const int n0 = blockIdx.x * 64;
    if (lengths[b] <= t0) return;

    __shared__ float As[16][128];
    __shared__ float Bs[16][64];
    __shared__ int   toks[128];

    const int tid = threadIdx.x;
    if (tid < 128) toks[tid] = ids[b*TT + t0 + tid];

    const int tx = tid & 15;
    const int ty = tid >> 4;
    float acc[8][4];
    #pragma unroll
    for (int i = 0; i < 8; i++)
        #pragma unroll
        for (int j = 0; j < 4; j++) acc[i][j] = 0.f;

    for (int k0 = 0; k0 < 300; k0 += 16) {
        __syncthreads();
        for (int l = tid; l < 512; l += 256) {
            int r  = l >> 2;
            int kq = l & 3;
            int k  = k0 + kq * 4;
            float4 v = make_float4(0.f, 0.f, 0.f, 0.f);
            if (k < 300) v = *(const float4*)(emb + (size_t)toks[r]*DD + k);
            As[kq*4+0][r] = v.x;
            As[kq*4+1][r] = v.y;
            As[kq*4+2][r] = v.z;
            As[kq*4+3][r] = v.w;
        }
        {
            int l  = tid;
            int kk = l >> 4;
            int q  = l & 15;
            int k  = k0 + kk;
            int n  = n0 + q * 4;
            float4 v = make_float4(0.f, 0.f, 0.f, 0.f);
            if (k < 300 && n < NG) v = *(const float4*)(W + (size_t)k*NG + n);
            *(float4*)&Bs[kk][q*4] = v;
        }
        __syncthreads();
        #pragma unroll
        for (int kk = 0; kk < 16; kk++) {
            float4 bv = *(const float4*)&Bs[kk][tx*4];
            float4 a0 = *(const float4*)&As[kk][ty*8];
            float4 a1 = *(const float4*)&As[kk][ty*8 + 4];
            float am[8] = {a0.x, a0.y, a0.z, a0.w, a1.x, a1.y, a1.z, a1.w};
            #pragma unroll
            for (int i = 0; i < 8; i++) {
                acc[i][0] += am[i] * bv.x;
                acc[i][1] += am[i] * bv.y;
                acc[i][2] += am[i] * bv.z;
                acc[i][3] += am[i] * bv.w;
            }
        }
    }

    const int n = n0 + tx * 4;
    if (n < NG) {
        float4 blv = *(const float4*)(bl + n);
        #pragma unroll
        for (int i = 0; i < 8; i++) {
            int t = t0 + ty*8 + i;
            float4 o;
            o.x = acc[i][0] + blv.x;
            o.y = acc[i][1] + blv.y;
            o.z = acc[i][2] + blv.z;
            o.w = acc[i][3] + blv.w;
            *(float4*)(g_xz + ((size_t)b*TT + t)*NG + n) = o;
        }
    }
}

// ---------------------------------------------------------------------------
// grid barrier: monotonic counter, release(fence)->arrive, acquire-spin.
// All 148 CTAs are co-resident (1/SM) so forward progress is guaranteed.
// ---------------------------------------------------------------------------
__device__ __forceinline__ void grid_barrier(unsigned int target) {
    __syncthreads();
    __threadfence();                       // release all prior global writes
    if (threadIdx.x == 0) {
        atomicAdd(&g_bar, 1u);
        unsigned int v;
        do {
            asm volatile("ld.acquire.gpu.u32 %0, [%1];"
                         : "=r"(v) : "l"(&g_bar) : "memory");
            if (v >= target) break;
            __nanosleep(32);
        } while (true);
    }
    __syncthreads();
}

// ---------------------------------------------------------------------------
// persistent recurrence kernel: W resident in smem, 512 steps, grid barrier
// between steps. Cross-SM state (h, c, xz) via ldcg/stcg (L2-coherent; no
// stale-L1 hazard). Buffer-parity invariant identical to the launch-per-step
// version: tile retires at t==maxlen with final state in buffer (maxlen&1).
// ---------------------------------------------------------------------------
__global__ __launch_bounds__(128) void lstm_persistent(
    const float* __restrict__ W,
    const int*   __restrict__ lengths)
{
    extern __shared__ float sm[];
    float* hs  = sm + SM_HS;
    float* wsT = sm + SM_WST;
    float* wsX = sm + SM_WSX;
    float* zs  = sm + SM_ZS;
    float* zsX = sm + SM_ZSX;
    int*   sl  = (int*)(sm + SM_SL);

    const int ntile = blockIdx.x % NTIL;
    const int mtile = blockIdx.x / NTIL;
    const int u0    = ntile * 8;              // base units u0..u0+7 (<=295)
    const int m0    = mtile * 32;
    const int ue    = (ntile < 4) ? (296 + ntile) : -1;  // extra unit (4 CTAs/m-tile)
    const int tid   = threadIdx.x;

    if (tid < 32) sl[tid] = lengths[m0 + tid];

    // resident W slice (loaded once for all 512 steps)
    for (int l = tid; l < 9600; l += 128) {
        int k  = l >> 5;
        int nn = l & 31;
        int u  = u0 + (nn & 7);
        int g  = nn >> 3;
        wsT[nn*HH + k] = W[(size_t)(HH + k)*NG + g*HH + u];
    }
    if (ue >= 0) {
        for (int l = tid; l < 1200; l += 128) {
            int g = l / 300;
            int k = l - g*300;
            wsX[g*HH + k] = W[(size_t)(HH + k)*NG + g*HH + ue];
        }
    }
    __syncthreads();
    if (tid < 32) {
        int v = sl[tid];
        #pragma unroll
        for (int o = 16; o; o >>= 1) v = max(v, __shfl_xor_sync(0xffffffffu, v, o));
        if (tid == 0) sl[32] = v;
    }
    __syncthreads();
    const int maxlen = sl[32];

    const int tx = tid & 15;   // 2 cols each -> 32
    const int ty = tid >> 4;   // 4 rows each -> 32
    const int mr = ty * 4;
    const int nc = tx * 2;

    for (int t = 0; t < TT; t++) {
        if (t < maxlen) {
            const int    p      = t & 1;
            const float* hread  = g_h[p];
            float*       hwrite = g_h[p ^ 1];

            // --- prefetch xz for this step's epilogue (hidden behind matmul) ---
            float pf[2][4];
            #pragma unroll
            for (int s = 0; s < 2; s++) {
                int l  = tid + s*128;
                int m  = l >> 3;
                int uu = l & 7;
                const float* xzp = g_xz + ((size_t)(m0+m)*TT + t)*NG + (u0 + uu);
                bool act = (t < sl[m]);
                pf[s][0] = act ? __ldcg(xzp)        : 0.f;
                pf[s][1] = act ? __ldcg(xzp + HH)   : 0.f;
                pf[s][2] = act ? __ldcg(xzp + 2*HH) : 0.f;
                pf[s][3] = act ? __ldcg(xzp + 3*HH) : 0.f;
            }
            float pfX[4] = {0.f, 0.f, 0.f, 0.f};
            if (ue >= 0 && tid < 32) {
                const float* xzp = g_xz + ((size_t)(m0+tid)*TT + t)*NG + ue;
                if (t < sl[tid]) {
                    pfX[0] = __ldcg(xzp);
                    pfX[1] = __ldcg(xzp + HH);
                    pfX[2] = __ldcg(xzp + 2*HH);
                    pfX[3] = __ldcg(xzp + 3*HH);
                }
            }

            // --- stage h tile (L2-only loads: written by other SMs last step) ---
            {
                const float4* gh4  = (const float4*)(hread + (size_t)m0 * HH);
                float4*       hs4w = (float4*)hs;
                for (int l = tid; l < 2400; l += 128) hs4w[l] = __ldcg(gh4 + l);
            }
            __syncthreads();

            // --- base matmul: z[32 m][32 n] = h[32x300] @ Wslice ---
            float acc[4][2];
            #pragma unroll
            for (int i = 0; i < 4; i++) { acc[i][0] = 0.f; acc[i][1] = 0.f; }
            const float4* hs4 = (const float4*)hs;
            const float4* ws4 = (const float4*)wsT;
            #pragma unroll 3
            for (int q = 0; q < 75; q++) {
                float4 w0 = ws4[(nc + 0)*75 + q];
                float4 w1 = ws4[(nc + 1)*75 + q];
                #pragma unroll
                for (int i = 0; i < 4; i++) {
                    float4 hv = hs4[(mr + i)*75 + q];
                    acc[i][0] += hv.x*w0.x + hv.y*w0.y + hv.z*w0.z + hv.w*w0.w;
                    acc[i][1] += hv.x*w1.x + hv.y*w1.y + hv.z*w1.z + hv.w*w1.w;
                }
            }
            #pragma unroll
            for (int i = 0; i < 4; i++) {
                zs[(mr + i)*32 + nc]     = acc[i][0];
                zs[(mr + i)*32 + nc + 1] = acc[i][1];
            }
            // --- extra-unit matmul: 128 outputs, 1/thread (uniform load) ---
            if (ue >= 0) {
                int me = tid >> 2;        // batch row 0..31
                int ge = tid & 3;         // gate
                const float4* wx4 = (const float4*)wsX;
                float ax = 0.f;
                #pragma unroll 5
                for (int q = 0; q < 75; q++) {
                    float4 hv = hs4[me*75 + q];
                    float4 wv = wx4[ge*75 + q];
                    ax += hv.x*wv.x + hv.y*wv.y + hv.z*wv.z + hv.w*wv.w;
                }
                zsX[me*4 + ge] = ax;
            }
            __syncthreads();

            // --- epilogue: gates + state update (base: 2 (m,u) pairs/thread) ---
            #pragma unroll
            for (int s = 0; s < 2; s++) {
                int l  = tid + s*128;
                int m  = l >> 3;
                int uu = l & 7;
                int b  = m0 + m;
                int u  = u0 + uu;
                int hidx = b*HH + u;
                if (t < sl[m]) {
                    float zi = zs[m*32 +      uu] + pf[s][0];
                    float zj = zs[m*32 +  8 + uu] + pf[s][1];
                    float zf = zs[m*32 + 16 + uu] + pf[s][2];
                    float zo = zs[m*32 + 24 + uu] + pf[s][3];
                    float si = 1.f / (1.f + expf(-zi));
                    float sf = 1.f / (1.f + expf(-(zf + 1.f)));  // FORGET_BIAS=1
                    float so = 1.f / (1.f + expf(-zo));
                    float tj = tanhf(zj);
                    float cold = __ldcg(&g_c[hidx]);
                    float cnew = cold * sf + si * tj;
                    float hnew = tanhf(cnew) * so;
                    __stcg(&g_c[hidx], cnew);
                    __stcg(&hwrite[hidx], hnew);
                } else {
                    __stcg(&hwrite[hidx], hs[m*HH + u]);  // carry frozen state
                }
            }
            if (ue >= 0 && tid < 32) {
                int b = m0 + tid;
                int hidx = b*HH + ue;
                if (t < sl[tid]) {
                    float zi = zsX[tid*4 + 0] + pfX[0];
                    float zj = zsX[tid*4 + 1] + pfX[1];
                    float zf = zsX[tid*4 + 2] + pfX[2];
                    float zo = zsX[tid*4 + 3] + pfX[3];
                    float si = 1.f / (1.f + expf(-zi));
                    float sf = 1.f / (1.f + expf(-(zf + 1.f)));
                    float so = 1.f / (1.f + expf(-zo));
                    float tj = tanhf(zj);
                    float cold = __ldcg(&g_c[hidx]);
                    float cnew = cold * sf + si * tj;
                    float hnew = tanhf(cnew) * so;
                    __stcg(&g_c[hidx], cnew);
                    __stcg(&hwrite[hidx], hnew);
                } else {
                    __stcg(&hwrite[hidx], hs[tid*HH + ue]);
                }
            }
        }
        grid_barrier((unsigned int)(t + 1) * NCTAS);
    }
}

// ---------------------------------------------------------------------------
// final: logits + mean NLL. Row b's final h is in buffer (tile maxlen & 1).
// ---------------------------------------------------------------------------
__global__ void final_kernel(
    const float* __restrict__ Wd,
    const float* __restrict__ bd,
    const int*   __restrict__ labels,
    const int*   __restrict__ lengths,
    float*       __restrict__ out,
    int out_size)
{
    __shared__ float red[128];
    __shared__ int   slen[128];
    int b = threadIdx.x;
    slen[b] = lengths[b];
    __syncthreads();

    int tile0 = b & ~31;
    int maxlen = 0;
    #pragma unroll 8
    for (int i = 0; i < 32; i++) maxlen = max(maxlen, slen[tile0 + i]);
    const float* h = g_h[maxlen & 1] + b*HH;

    float a0 = bd[0], a1 = bd[1], a2 = bd[2];
    for (int k = 0; k < HH; k++) {
        float hv = h[k];
        a0 += hv * Wd[k*3 + 0];
        a1 += hv * Wd[k*3 + 1];
        a2 += hv * Wd[k*3 + 2];
    }
    float mx  = fmaxf(a0, fmaxf(a1, a2));
    float lse = mx + logf(expf(a0 - mx) + expf(a1 - mx) + expf(a2 - mx));
    int   lab = labels[b];
    float sel = (lab == 0) ? a0 : ((lab == 1) ? a1 : a2);
    float nll = lse - sel;

    int off = (out_size >= 385) ? 1 : 0;
    if (out_size >= 384) {
        out[off + b*3 + 0] = a0;
        out[off + b*3 + 1] = a1;
        out[off + b*3 + 2] = a2;
    }
    red[b] = nll;
    __syncthreads();
    for (int s = 64; s; s >>= 1) {
        if (b < s) red[b] += red[b + s];
        __syncthreads();
    }
    if (b == 0 && (off == 1 || out_size < 384)) out[0] = red[0] * (1.f / 128.f);
}

// ---------------------------------------------------------------------------
extern "C" void kernel_launch(void* const* d_in, const int* in_sizes, int n_in,
                              void* d_out, int out_size)
{
    const int*   ids     = (const int*)  d_in[0];
    const int*   lengths = (const int*)  d_in[1];
    const int*   labels  = (const int*)  d_in[2];
    const float* emb     = (const float*)d_in[3];
    const float* W       = (const float*)d_in[4];
    const float* bl      = (const float*)d_in[5];
    const float* Wd      = (const float*)d_in[6];
    const float* bd      = (const float*)d_in[7];
    float* out = (float*)d_out;

    cudaFuncSetAttribute(lstm_persistent,
                         cudaFuncAttributeMaxDynamicSharedMemorySize,
                         PERS_SMEM_BYTES);

    init_kernel<<<(BB*HH + 255)/256, 256>>>();
    precompute_kernel<<<dim3(19, 4, BB), 256>>>(ids, lengths, emb, W, bl);
    lstm_persistent<<<NCTAS, 128, PERS_SMEM_BYTES>>>(W, lengths);
    final_kernel<<<1, 128>>>(Wd, bd, labels, lengths, out, out_size);
}

// round 6
// speedup vs baseline: 2.1347x; 1.3968x over previous
#include <cuda_runtime.h>
#include <math.h>

#define BB 128
#define TT 512
#define DD 300
#define HH 300
#define NG 1200    // 4*H
#define NTIL 38    // n-tiles per m-group (38*8 = 304 >= 300)
#define NGRP 4     // m-groups of 32 rows
#define NCTAS (NTIL*NGRP)   // 152 == GB300 SM count

// ---- device scratch (static: the sanctioned alloc-free path) ----
__device__ float g_h[2][BB*HH];          // double-buffered hidden state
__device__ float g_xz[(size_t)BB*TT*NG]; // precomputed x@Wx + b_lstm
__device__ unsigned int g_barg[NGRP*32]; // per-group barrier counters (128B apart)

// persistent-kernel smem layout (floats)
#define SM_HS   0        // [32][300] h tile
#define SM_WST  9600     // [32 n][300 k] W slice (n = g*8+uu)
#define SM_SL   19200    // [33] lengths + max
#define SM_TOT  19240
#define PERS_SMEM_BYTES (SM_TOT*4)

// ---------------------------------------------------------------------------
__global__ void init_kernel() {
    int i = blockIdx.x * blockDim.x + threadIdx.x;
    if (i < BB*HH) {
        g_h[0][i] = 0.f;
        g_h[1][i] = 0.f;
    }
    if (i < NGRP*32) g_barg[i] = 0u;
}

// ---------------------------------------------------------------------------
// precompute: g_xz[b][t][n] = embedding[ids[b][t]] @ W_lstm[0:300, n] + b_lstm[n]
// (unchanged from passing version)
// ---------------------------------------------------------------------------
__global__ __launch_bounds__(256) void precompute_kernel(
    const int*   __restrict__ ids,
    const int*   __restrict__ lengths,
    const float* __restrict__ emb,
    const float* __restrict__ W,
    const float* __restrict__ bl)
{
    const int b  = blockIdx.z;
    const int t0 = blockIdx.y * 128;
    const int n0 = blockIdx.x * 64;
    if (lengths[b] <= t0) return;

    __shared__ float As[16][128];
    __shared__ float Bs[16][64];
    __shared__ int   toks[128];

    const int tid = threadIdx.x;
    if (tid < 128) toks[tid] = ids[b*TT + t0 + tid];

    const int tx = tid & 15;
    const int ty = tid >> 4;
    float acc[8][4];
    #pragma unroll
    for (int i = 0; i < 8; i++)
        #pragma unroll
        for (int j = 0; j < 4; j++) acc[i][j] = 0.f;

    for (int k0 = 0; k0 < 300; k0 += 16) {
        __syncthreads();
        for (int l = tid; l < 512; l += 256) {
            int r  = l >> 2;
            int kq = l & 3;
            int k  = k0 + kq * 4;
            float4 v = make_float4(0.f, 0.f, 0.f, 0.f);
            if (k < 300) v = *(const float4*)(emb + (size_t)toks[r]*DD + k);
            As[kq*4+0][r] = v.x;
            As[kq*4+1][r] = v.y;
            As[kq*4+2][r] = v.z;
            As[kq*4+3][r] = v.w;
        }
        {
            int l  = tid;
            int kk = l >> 4;
            int q  = l & 15;
            int k  = k0 + kk;
            int n  = n0 + q * 4;
            float4 v = make_float4(0.f, 0.f, 0.f, 0.f);
            if (k < 300 && n < NG) v = *(const float4*)(W + (size_t)k*NG + n);
            *(float4*)&Bs[kk][q*4] = v;
        }
        __syncthreads();
        #pragma unroll
        for (int kk = 0; kk < 16; kk++) {
            float4 bv = *(const float4*)&Bs[kk][tx*4];
            float4 a0 = *(const float4*)&As[kk][ty*8];
            float4 a1 = *(const float4*)&As[kk][ty*8 + 4];
            float am[8] = {a0.x, a0.y, a0.z, a0.w, a1.x, a1.y, a1.z, a1.w};
            #pragma unroll
            for (int i = 0; i < 8; i++) {
                acc[i][0] += am[i] * bv.x;
                acc[i][1] += am[i] * bv.y;
                acc[i][2] += am[i] * bv.z;
                acc[i][3] += am[i] * bv.w;
            }
        }
    }

    const int n = n0 + tx * 4;
    if (n < NG) {
        float4 blv = *(const float4*)(bl + n);
        #pragma unroll
        for (int i = 0; i < 8; i++) {
            int t = t0 + ty*8 + i;
            float4 o;
            o.x = acc[i][0] + blv.x;
            o.y = acc[i][1] + blv.y;
            o.z = acc[i][2] + blv.z;
            o.w = acc[i][3] + blv.w;
            *(float4*)(g_xz + ((size_t)b*TT + t)*NG + n) = o;
        }
    }
}

// ---------------------------------------------------------------------------
// persistent recurrence kernel v2.
// grid = 152 CTAs (4 m-groups x 38 n-tiles), 256 threads.
// Per-m-group software barrier (38 arrivals). c is register-resident.
// Thread (mm = tid>>3, uu = tid&7) owns unit u = u0+uu of row b = m0+mm,
// computes all 4 gate dot-products itself -> no z round-trip, no mid sync.
// h goes via global (ldcg/stcg, ordered by the group barrier's fence/acquire).
// Buffer-parity invariant: group retires at t==maxlen with final state in
// buffer (maxlen & 1); final_kernel recomputes maxlen per 32-row tile.
// ---------------------------------------------------------------------------
__global__ __launch_bounds__(256) void lstm_persistent(
    const float* __restrict__ W,
    const int*   __restrict__ lengths)
{
    extern __shared__ float sm[];
    float* hs  = sm + SM_HS;    // [32][300]
    float* wsT = sm + SM_WST;   // [32 n][300 k]
    int*   sl  = (int*)(sm + SM_SL);

    const int gidx  = blockIdx.x / NTIL;   // m-group
    const int ntile = blockIdx.x % NTIL;
    const int u0    = ntile * 8;
    const int m0    = gidx * 32;
    const int tid   = threadIdx.x;
    const int uu    = tid & 7;
    const int mm    = tid >> 3;            // 0..31
    const int b     = m0 + mm;
    const int u     = u0 + uu;
    const bool uval = (u < HH);

    if (tid < 32) sl[tid] = lengths[m0 + tid];

    // resident W slice: wsT[nn][k] = W[300+k][ (nn>>3)*300 + u0 + (nn&7) ]
    for (int l = tid; l < 9600; l += 256) {
        int k  = l >> 5;
        int nn = l & 31;
        int us = u0 + (nn & 7);
        wsT[nn*HH + k] = (us < HH) ? W[(size_t)(HH + k)*NG + (nn >> 3)*HH + us] : 0.f;
    }
    __syncthreads();
    if (tid < 32) {
        int v = sl[tid];
        #pragma unroll
        for (int o = 16; o; o >>= 1) v = max(v, __shfl_xor_sync(0xffffffffu, v, o));
        if (tid == 0) sl[32] = v;
    }
    __syncthreads();
    const int maxlen = sl[32];
    const int mylen  = sl[mm];

    unsigned int* barp = &g_barg[gidx * 32];

    const float4* h4 = (const float4*)(hs + mm*HH);
    const float4* w0 = (const float4*)(wsT + ( 0 + uu)*HH);
    const float4* w1 = (const float4*)(wsT + ( 8 + uu)*HH);
    const float4* w2 = (const float4*)(wsT + (16 + uu)*HH);
    const float4* w3 = (const float4*)(wsT + (24 + uu)*HH);

    float c_reg = 0.f;   // cell state for (b, u): owner-exclusive -> register

    for (int t = 0; t < maxlen; t++) {
        const float* hread  = g_h[t & 1];
        float*       hwrite = g_h[(t & 1) ^ 1];
        const bool   act    = uval && (t < mylen);

        // prefetch xz (epilogue operands) — hidden behind staging+matmul
        const float* xzp = g_xz + ((size_t)b*TT + t)*NG + u;
        float pf0 = act ? __ldcg(xzp + 0*HH) : 0.f;
        float pf1 = act ? __ldcg(xzp + 1*HH) : 0.f;
        float pf2 = act ? __ldcg(xzp + 2*HH) : 0.f;
        float pf3 = act ? __ldcg(xzp + 3*HH) : 0.f;

        // stage h tile (cross-SM data -> L2-coherent loads)
        {
            const float4* gh4  = (const float4*)(hread + (size_t)m0 * HH);
            float4*       hs4w = (float4*)hs;
            for (int l = tid; l < 2400; l += 256) hs4w[l] = __ldcg(gh4 + l);
        }
        __syncthreads();

        // 4 gate dot-products for (b, u)
        float a0 = 0.f, a1 = 0.f, a2 = 0.f, a3 = 0.f;
        #pragma unroll 5
        for (int q = 0; q < 75; q++) {
            float4 hv = h4[q];
            float4 v0 = w0[q];
            float4 v1 = w1[q];
            float4 v2 = w2[q];
            float4 v3 = w3[q];
            a0 += hv.x*v0.x + hv.y*v0.y + hv.z*v0.z + hv.w*v0.w;
            a1 += hv.x*v1.x + hv.y*v1.y + hv.z*v1.z + hv.w*v1.w;
            a2 += hv.x*v2.x + hv.y*v2.y + hv.z*v2.z + hv.w*v2.w;
            a3 += hv.x*v3.x + hv.y*v3.y + hv.z*v3.z + hv.w*v3.w;
        }

        // epilogue (thread-local; no sync needed)
        if (act) {
            float zi = a0 + pf0;
            float zj = a1 + pf1;
            float zf = a2 + pf2;
            float zo = a3 + pf3;
            float si = 1.f / (1.f + expf(-zi));
            float sf = 1.f / (1.f + expf(-(zf + 1.f)));  // FORGET_BIAS=1
            float so = 1.f / (1.f + expf(-zo));
            float tj = tanhf(zj);
            c_reg = c_reg * sf + si * tj;
            float hnew = tanhf(c_reg) * so;
            __stcg(&hwrite[b*HH + u], hnew);
        } else if (uval) {
            __stcg(&hwrite[b*HH + u], hs[mm*HH + u]);   // carry frozen state
        }

        // per-group barrier: release -> arrive -> acquire-spin
        __syncthreads();
        __threadfence();
        if (tid == 0) {
            atomicAdd(barp, 1u);
            const unsigned int target = (unsigned int)(t + 1) * NTIL;
            unsigned int v;
            do {
                asm volatile("ld.acquire.gpu.u32 %0, [%1];"
                             : "=r"(v) : "l"(barp) : "memory");
                if (v >= target) break;
                __nanosleep(20);
            } while (true);
        }
        __syncthreads();
    }
}

// ---------------------------------------------------------------------------
// final: logits + mean NLL. Row b's final h is in buffer (tile maxlen & 1).
// ---------------------------------------------------------------------------
__global__ void final_kernel(
    const float* __restrict__ Wd,
    const float* __restrict__ bd,
    const int*   __restrict__ labels,
    const int*   __restrict__ lengths,
    float*       __restrict__ out,
    int out_size)
{
    __shared__ float red[128];
    __shared__ int   slen[128];
    int b = threadIdx.x;
    slen[b] = lengths[b];
    __syncthreads();

    int tile0 = b & ~31;
    int maxlen = 0;
    #pragma unroll 8
    for (int i = 0; i < 32; i++) maxlen = max(maxlen, slen[tile0 + i]);
    const float* h = g_h[maxlen & 1] + b*HH;

    float a0 = bd[0], a1 = bd[1], a2 = bd[2];
    for (int k = 0; k < HH; k++) {
        float hv = h[k];
        a0 += hv * Wd[k*3 + 0];
        a1 += hv * Wd[k*3 + 1];
        a2 += hv * Wd[k*3 + 2];
    }
    float mx  = fmaxf(a0, fmaxf(a1, a2));
    float lse = mx + logf(expf(a0 - mx) + expf(a1 - mx) + expf(a2 - mx));
    int   lab = labels[b];
    float sel = (lab == 0) ? a0 : ((lab == 1) ? a1 : a2);
    float nll = lse - sel;

    int off = (out_size >= 385) ? 1 : 0;
    if (out_size >= 384) {
        out[off + b*3 + 0] = a0;
        out[off + b*3 + 1] = a1;
        out[off + b*3 + 2] = a2;
    }
    red[b] = nll;
    __syncthreads();
    for (int s = 64; s; s >>= 1) {
        if (b < s) red[b] += red[b + s];
        __syncthreads();
    }
    if (b == 0 && (off == 1 || out_size < 384)) out[0] = red[0] * (1.f / 128.f);
}

// ---------------------------------------------------------------------------
extern "C" void kernel_launch(void* const* d_in, const int* in_sizes, int n_in,
                              void* d_out, int out_size)
{
    const int*   ids     = (const int*)  d_in[0];
    const int*   lengths = (const int*)  d_in[1];
    const int*   labels  = (const int*)  d_in[2];
    const float* emb     = (const float*)d_in[3];
    const float* W       = (const float*)d_in[4];
    const float* bl      = (const float*)d_in[5];
    const float* Wd      = (const float*)d_in[6];
    const float* bd      = (const float*)d_in[7];
    float* out = (float*)d_out;

    cudaFuncSetAttribute(lstm_persistent,
                         cudaFuncAttributeMaxDynamicSharedMemorySize,
                         PERS_SMEM_BYTES);

    init_kernel<<<(BB*HH + 255)/256, 256>>>();
    precompute_kernel<<<dim3(19, 4, BB), 256>>>(ids, lengths, emb, W, bl);
    lstm_persistent<<<NCTAS, 256, PERS_SMEM_BYTES>>>(W, lengths);
    final_kernel<<<1, 128>>>(Wd, bd, labels, lengths, out, out_size);
}

// round 7
// speedup vs baseline: 2.1879x; 1.0249x over previous
#include <cuda_runtime.h>
#include <math.h>

#define BB 128
#define TT 512
#define DD 300
#define HH 300
#define NG 1200    // 4*H
#define NTIL 38    // n-tiles per m-group (38*8 = 304 >= 300)
#define NGRP 4     // m-groups of 32 rows
#define NCTAS (NTIL*NGRP)   // 152 == GB300 SM count
#define KPAD 304   // padded k (8 chunks of 38)

typedef unsigned long long u64;

// ---- packed f32x2 helpers (FFMA2: only reachable via PTX) ----
__device__ __forceinline__ u64 f2pack(float lo, float hi) {
    u64 d; asm("mov.b64 %0, {%1, %2};" : "=l"(d) : "f"(lo), "f"(hi)); return d;
}
__device__ __forceinline__ void f2unpack(u64 v, float& lo, float& hi) {
    asm("mov.b64 {%0, %1}, %2;" : "=f"(lo), "=f"(hi) : "l"(v));
}
__device__ __forceinline__ u64 f2fma(u64 a, u64 b, u64 c) {
    u64 d; asm("fma.rn.f32x2 %0, %1, %2, %3;" : "=l"(d) : "l"(a), "l"(b), "l"(c)); return d;
}
__device__ __forceinline__ u64 f2add(u64 a, u64 b) {
    u64 d; asm("add.rn.f32x2 %0, %1, %2;" : "=l"(d) : "l"(a), "l"(b)); return d;
}

// ---- device scratch ----
__device__ float g_h[2][BB*HH];          // double-buffered hidden state
__device__ float g_xz[(size_t)BB*TT*NG]; // precomputed x@Wx + b_lstm
__device__ unsigned int g_barg[NGRP*32]; // per-group barrier counters (128B apart)

// persistent-kernel smem layout (floats)
#define SM_HS   0                 // [32][KPAD] h tile (padded, cols 300..303 zero)
#define SM_ZS   (32*KPAD)         // [32 m][32 col] z  (col = unit*4 + gate)
#define SM_SL   (32*KPAD + 1024)  // [33] lengths + max
#define SM_TOT  (32*KPAD + 1024 + 40)
#define PERS_SMEM_BYTES (SM_TOT*4)

// ---------------------------------------------------------------------------
__global__ void init_kernel() {
    int i = blockIdx.x * blockDim.x + threadIdx.x;
    if (i < BB*HH) {
        g_h[0][i] = 0.f;
        g_h[1][i] = 0.f;
    }
    if (i < NGRP*32) g_barg[i] = 0u;
}

// ---------------------------------------------------------------------------
// precompute: g_xz[b][t][n] = embedding[ids[b][t]] @ W_lstm[0:300, n] + b_lstm[n]
// FFMA2 version: m-pairs packed (direct 64-bit loads from As), b duplicated.
// ---------------------------------------------------------------------------
__global__ __launch_bounds__(256) void precompute_kernel(
    const int*   __restrict__ ids,
    const int*   __restrict__ lengths,
    const float* __restrict__ emb,
    const float* __restrict__ W,
    const float* __restrict__ bl)
{
    const int b  = blockIdx.z;
    const int t0 = blockIdx.y * 128;
    const int n0 = blockIdx.x * 64;
    if (lengths[b] <= t0) return;

    __shared__ float As[16][128];
    __shared__ float Bs[16][64];
    __shared__ int   toks[128];

    const int tid = threadIdx.x;
    if (tid < 128) toks[tid] = ids[b*TT + t0 + tid];

    const int tx = tid & 15;   // n: 4 cols each
    const int ty = tid >> 4;   // m: 8 rows each (4 pairs)
    u64 acc2[4][4];
    #pragma unroll
    for (int i = 0; i < 4; i++)
        #pragma unroll
        for (int j = 0; j < 4; j++) acc2[i][j] = 0ull;

    for (int k0 = 0; k0 < 300; k0 += 16) {
        __syncthreads();
        for (int l = tid; l < 512; l += 256) {
            int r  = l >> 2;
            int kq = l & 3;
            int k  = k0 + kq * 4;
            float4 v = make_float4(0.f, 0.f, 0.f, 0.f);
            if (k < 300) v = *(const float4*)(emb + (size_t)toks[r]*DD + k);
            As[kq*4+0][r] = v.x;
            As[kq*4+1][r] = v.y;
            As[kq*4+2][r] = v.z;
            As[kq*4+3][r] = v.w;
        }
        {
            int l  = tid;
            int kk = l >> 4;
            int q  = l & 15;
            int k  = k0 + kk;
            int n  = n0 + q * 4;
            float4 v = make_float4(0.f, 0.f, 0.f, 0.f);
            if (k < 300 && n < NG) v = *(const float4*)(W + (size_t)k*NG + n);
            *(float4*)&Bs[kk][q*4] = v;
        }
        __syncthreads();
        #pragma unroll
        for (int kk = 0; kk < 16; kk++) {
            float4 bv = *(const float4*)&Bs[kk][tx*4];
            u64 b0 = f2pack(bv.x, bv.x);
            u64 b1 = f2pack(bv.y, bv.y);
            u64 b2 = f2pack(bv.z, bv.z);
            u64 b3 = f2pack(bv.w, bv.w);
            const u64* a2 = (const u64*)&As[kk][ty*8];   // 4 m-pairs, 8B-aligned
            #pragma unroll
            for (int mp = 0; mp < 4; mp++) {
                u64 av = a2[mp];
                acc2[mp][0] = f2fma(av, b0, acc2[mp][0]);
                acc2[mp][1] = f2fma(av, b1, acc2[mp][1]);
                acc2[mp][2] = f2fma(av, b2, acc2[mp][2]);
                acc2[mp][3] = f2fma(av, b3, acc2[mp][3]);
            }
        }
    }

    const int n = n0 + tx * 4;
    if (n < NG) {
        float4 blv = *(const float4*)(bl + n);
        #pragma unroll
        for (int mp = 0; mp < 4; mp++) {
            float x0,x1,y0,y1,z0,z1,q0,q1;
            f2unpack(acc2[mp][0], x0, x1);
            f2unpack(acc2[mp][1], y0, y1);
            f2unpack(acc2[mp][2], z0, z1);
            f2unpack(acc2[mp][3], q0, q1);
            int t = t0 + ty*8 + 2*mp;
            float4 o0 = make_float4(x0+blv.x, y0+blv.y, z0+blv.z, q0+blv.w);
            float4 o1 = make_float4(x1+blv.x, y1+blv.y, z1+blv.z, q1+blv.w);
            *(float4*)(g_xz + ((size_t)b*TT + t  )*NG + n) = o0;
            *(float4*)(g_xz + ((size_t)b*TT + t+1)*NG + n) = o1;
        }
    }
}

// ---------------------------------------------------------------------------
// persistent recurrence kernel v3: W register-resident, FFMA2 matmul.
// grid = 152 CTAs (4 m-groups x 38 n-tiles), 256 threads.
// Matmul mapping: warp wid (0..7) owns unit u0+wid; lane = kc*4 + gate:
//   kc = k-chunk (38 k each, k padded to 304), gate in {i,j,f,o}.
//   Thread holds its 38 W values as 19 f32x2 regs for all 512 steps.
//   Per step: za[m] = sum_{k in chunk} w[k]*h[m][k]; shfl-reduce over kc;
//   z exchanged via smem tile [32 m][32 col], col = unit*4 + gate.
// Epilogue mapping: thread (mm = tid>>3, uu = tid&7) owns (row m0+mm, unit
//   u0+uu); c register-resident; h via ldcg/stcg ordered by group barrier.
// Buffer-parity invariant unchanged (group retires at its maxlen, final
// state in buffer maxlen&1).
// ---------------------------------------------------------------------------
__global__ __launch_bounds__(256) void lstm_persistent(
    const float* __restrict__ W,
    const int*   __restrict__ lengths)
{
    extern __shared__ float sm[];
    float* hs  = sm + SM_HS;    // [32][KPAD]
    float* zsm = sm + SM_ZS;    // [32][32]
    int*   sl  = (int*)(sm + SM_SL);

    const int gidx  = blockIdx.x / NTIL;   // m-group
    const int ntile = blockIdx.x % NTIL;
    const int u0    = ntile * 8;
    const int m0    = gidx * 32;
    const int tid   = threadIdx.x;
    const int wid   = tid >> 5;            // warp = unit slot 0..7
    const int lane  = tid & 31;
    const int kc    = lane >> 2;           // k-chunk 0..7
    const int gg    = lane & 3;            // gate
    const int u_mm  = u0 + wid;            // matmul unit

    // epilogue mapping
    const int  e_mm   = tid >> 3;
    const int  e_uu   = tid & 7;
    const int  e_u    = u0 + e_uu;
    const int  e_b    = m0 + e_mm;
    const bool e_uval = (e_u < HH);

    if (tid < 32) sl[tid] = lengths[m0 + tid];
    // zero hs padding columns 300..303 (written once; staging never touches them)
    if (tid < 128) hs[(tid >> 2)*KPAD + 300 + (tid & 3)] = 0.f;

    // W slice -> registers (step-invariant): w2[i] packs W[300+k][gg*300+u_mm]
    // for k = kc*38 + 2i, 2i+1
    u64 w2[19];
    {
        const bool uv = (u_mm < HH);
        const int  c  = gg*HH + (uv ? u_mm : 0);
        #pragma unroll
        for (int i = 0; i < 19; i++) {
            int k0 = kc*38 + 2*i;
            float lo = (uv && k0     < HH) ? W[(size_t)(HH + k0    )*NG + c] : 0.f;
            float hi = (uv && k0 + 1 < HH) ? W[(size_t)(HH + k0 + 1)*NG + c] : 0.f;
            w2[i] = f2pack(lo, hi);
        }
    }
    __syncthreads();
    if (tid < 32) {
        int v = sl[tid];
        #pragma unroll
        for (int o = 16; o; o >>= 1) v = max(v, __shfl_xor_sync(0xffffffffu, v, o));
        if (tid == 0) sl[32] = v;
    }
    __syncthreads();
    const int maxlen = sl[32];
    const int e_len  = sl[e_mm];

    unsigned int* barp = &g_barg[gidx * 32];

    float c_reg = 0.f;   // cell state for (e_b, e_u): owner-exclusive register

    for (int t = 0; t < maxlen; t++) {
        const float* hread  = g_h[t & 1];
        float*       hwrite = g_h[(t & 1) ^ 1];
        const bool   act    = e_uval && (t < e_len);

        // prefetch xz (epilogue operands)
        const float* xzp = g_xz + ((size_t)e_b*TT + t)*NG + e_u;
        float pf0 = act ? __ldcg(xzp + 0*HH) : 0.f;
        float pf1 = act ? __ldcg(xzp + 1*HH) : 0.f;
        float pf2 = act ? __ldcg(xzp + 2*HH) : 0.f;
        float pf3 = act ? __ldcg(xzp + 3*HH) : 0.f;

        // stage h tile into padded smem rows
        {
            const float4* gh4 = (const float4*)(hread + (size_t)m0 * HH);
            for (int l = tid; l < 2400; l += 256) {
                int m = l / 75;
                int i = l - m*75;
                *(float4*)&hs[m*KPAD + i*4] = __ldcg(gh4 + l);
            }
        }
        __syncthreads();

        // matmul: per m, partial dot over this thread's k-chunk; reduce over kc
        #pragma unroll 4
        for (int m = 0; m < 32; m++) {
            const u64* h2 = (const u64*)(hs + m*KPAD + kc*38);
            u64 a0 = 0ull, a1 = 0ull;
            #pragma unroll
            for (int i = 0; i < 18; i += 2) {
                a0 = f2fma(w2[i],   h2[i],   a0);
                a1 = f2fma(w2[i+1], h2[i+1], a1);
            }
            a0 = f2fma(w2[18], h2[18], a0);
            u64 s = f2add(a0, a1);
            float lo, hi; f2unpack(s, lo, hi);
            float v = lo + hi;
            v += __shfl_xor_sync(0xffffffffu, v, 4);
            v += __shfl_xor_sync(0xffffffffu, v, 8);
            v += __shfl_xor_sync(0xffffffffu, v, 16);
            zsm[m*32 + wid*4 + gg] = v;   // 8-way duplicate write, identical value
        }
        __syncthreads();

        // epilogue (thread-local c; gates contiguous in zsm -> one LDS.128)
        if (act) {
            float4 zv = *(const float4*)&zsm[e_mm*32 + e_uu*4];
            float zi = zv.x + pf0;
            float zj = zv.y + pf1;
            float zf = zv.z + pf2;
            float zo = zv.w + pf3;
            float si = 1.f / (1.f + __expf(-zi));
            float sf = 1.f / (1.f + __expf(-(zf + 1.f)));  // FORGET_BIAS=1
            float so = 1.f / (1.f + __expf(-zo));
            float tj = tanhf(zj);
            c_reg = c_reg * sf + si * tj;
            float hnew = tanhf(c_reg) * so;
            __stcg(&hwrite[e_b*HH + e_u], hnew);
        } else if (e_uval) {
            __stcg(&hwrite[e_b*HH + e_u], hs[e_mm*KPAD + e_u]);  // carry frozen
        }

        // per-group barrier: release -> arrive -> acquire-spin
        __syncthreads();
        __threadfence();
        if (tid == 0) {
            atomicAdd(barp, 1u);
            const unsigned int target = (unsigned int)(t + 1) * NTIL;
            unsigned int v;
            do {
                asm volatile("ld.acquire.gpu.u32 %0, [%1];"
                             : "=r"(v) : "l"(barp) : "memory");
                if (v >= target) break;
                __nanosleep(20);
            } while (true);
        }
        __syncthreads();
    }
}

// ---------------------------------------------------------------------------
// final: logits + mean NLL. Row b's final h is in buffer (tile maxlen & 1).
// ---------------------------------------------------------------------------
__global__ void final_kernel(
    const float* __restrict__ Wd,
    const float* __restrict__ bd,
    const int*   __restrict__ labels,
    const int*   __restrict__ lengths,
    float*       __restrict__ out,
    int out_size)
{
    __shared__ float red[128];
    __shared__ int   slen[128];
    __shared__ float wd_s[900];
    int b = threadIdx.x;
    slen[b] = lengths[b];
    for (int i = b; i < 900; i += 128) wd_s[i] = Wd[i];
    __syncthreads();

    int tile0 = b & ~31;
    int maxlen = 0;
    #pragma unroll 8
    for (int i = 0; i < 32; i++) maxlen = max(maxlen, slen[tile0 + i]);
    const float* h = g_h[maxlen & 1] + b*HH;

    float a0 = bd[0], a1 = bd[1], a2 = bd[2];
    #pragma unroll 5
    for (int k = 0; k < HH; k += 4) {
        float4 hv = *(const float4*)(h + k);
        a0 += hv.x*wd_s[(k+0)*3+0] + hv.y*wd_s[(k+1)*3+0]
            + hv.z*wd_s[(k+2)*3+0] + hv.w*wd_s[(k+3)*3+0];
        a1 += hv.x*wd_s[(k+0)*3+1] + hv.y*wd_s[(k+1)*3+1]
            + hv.z*wd_s[(k+2)*3+1] + hv.w*wd_s[(k+3)*3+1];
        a2 += hv.x*wd_s[(k+0)*3+2] + hv.y*wd_s[(k+1)*3+2]
            + hv.z*wd_s[(k+2)*3+2] + hv.w*wd_s[(k+3)*3+2];
    }
    float mx  = fmaxf(a0, fmaxf(a1, a2));
    float lse = mx + logf(expf(a0 - mx) + expf(a1 - mx) + expf(a2 - mx));
    int   lab = labels[b];
    float sel = (lab == 0) ? a0 : ((lab == 1) ? a1 : a2);
    float nll = lse - sel;

    int off = (out_size >= 385) ? 1 : 0;
    if (out_size >= 384) {
        out[off + b*3 + 0] = a0;
        out[off + b*3 + 1] = a1;
        out[off + b*3 + 2] = a2;
    }
    red[b] = nll;
    __syncthreads();
    for (int s = 64; s; s >>= 1) {
        if (b < s) red[b] += red[b + s];
        __syncthreads();
    }
    if (b == 0 && (off == 1 || out_size < 384)) out[0] = red[0] * (1.f / 128.f);
}

// ---------------------------------------------------------------------------
extern "C" void kernel_launch(void* const* d_in, const int* in_sizes, int n_in,
                              void* d_out, int out_size)
{
    const int*   ids     = (const int*)  d_in[0];
    const int*   lengths = (const int*)  d_in[1];
    const int*   labels  = (const int*)  d_in[2];
    const float* emb     = (const float*)d_in[3];
    const float* W       = (const float*)d_in[4];
    const float* bl      = (const float*)d_in[5];
    const float* Wd      = (const float*)d_in[6];
    const float* bd      = (const float*)d_in[7];
    float* out = (float*)d_out;

    cudaFuncSetAttribute(lstm_persistent,
                         cudaFuncAttributeMaxDynamicSharedMemorySize,
                         PERS_SMEM_BYTES);

    init_kernel<<<(BB*HH + 255)/256, 256>>>();
    precompute_kernel<<<dim3(19, 4, BB), 256>>>(ids, lengths, emb, W, bl);
    lstm_persistent<<<NCTAS, 256, PERS_SMEM_BYTES>>>(W, lengths);
    final_kernel<<<1, 128>>>(Wd, bd, labels, lengths, out, out_size);
}